// round 4
// baseline (speedup 1.0000x reference)
#include <cuda_runtime.h>

#define NB    4096
#define ND    1024
#define NC    10
#define TILE  64
#define KC    16          // k elements per smem stage
#define NCHUNK (ND / KC)  // 64
#define MAXT  4160        // worst-case active tiles (one class: 64*65/2 = 2080) + slack
#define GGRID 296         // k_gram grid: one full wave at occupancy 2

// ---------------- device scratch (no allocations allowed) ----------------
__device__ float2 g_pk[NB * ND];   // interleaved (ghat, xhat) unit-norm rows, 32 MB
__device__ int    g_cls[NB];
__device__ int    g_counts[NC];
__device__ int    g_offsets[NC];
__device__ int    g_order[NB];     // row indices stably sorted by class
__device__ int    g_tiles[MAXT];   // packed active tiles: c | ti<<4 | tj<<10
__device__ int    g_ntiles;
__device__ float  g_partials[MAXT];

// packed f32x2 FMA: d.lo += a.lo*b.lo ; d.hi += a.hi*b.hi   (SASS FFMA2)
__device__ __forceinline__ void ffma2(unsigned long long& d,
                                      unsigned long long a,
                                      unsigned long long b) {
    asm("fma.rn.f32x2 %0, %1, %2, %0;" : "+l"(d) : "l"(a), "l"(b));
}

// swizzled tile address: 128B rows, 16B slots XOR-swizzled by row&7
__device__ __forceinline__ float4* tile_ptr(char* base, int row, int c) {
    return reinterpret_cast<float4*>(base + row * 128 + ((c ^ (row & 7)) << 4));
}

// ---------------- kernel 0: zero class counters ----------------
__global__ void k_zero() {
    if (threadIdx.x < NC) g_counts[threadIdx.x] = 0;
}

// ---------------- kernel 1: per-row preprocess ----------------
// One block/row, 256 threads, 4 floats each. Min-max normalize grad, unit-
// normalize both vectors, write interleaved (g,x) pairs, argmax class.
__global__ void __launch_bounds__(256) k_prep(const float* __restrict__ outputs,
                                              const float* __restrict__ grad,
                                              const float* __restrict__ xin) {
    const int row = blockIdx.x;
    const int tid = threadIdx.x;

    const float4 gv = reinterpret_cast<const float4*>(grad + row * ND)[tid];
    const float4 xv = reinterpret_cast<const float4*>(xin  + row * ND)[tid];

    float mn = fminf(fminf(gv.x, gv.y), fminf(gv.z, gv.w));
    float mx = fmaxf(fmaxf(gv.x, gv.y), fmaxf(gv.z, gv.w));
#pragma unroll
    for (int o = 16; o > 0; o >>= 1) {
        mn = fminf(mn, __shfl_xor_sync(0xffffffffu, mn, o));
        mx = fmaxf(mx, __shfl_xor_sync(0xffffffffu, mx, o));
    }
    __shared__ float smn[8], smx[8], ssg[8], ssx[8];
    const int w = tid >> 5, lane = tid & 31;
    if (lane == 0) { smn[w] = mn; smx[w] = mx; }
    __syncthreads();
    mn = smn[0]; mx = smx[0];
#pragma unroll
    for (int i = 1; i < 8; i++) { mn = fminf(mn, smn[i]); mx = fmaxf(mx, smx[i]); }

    const float inv = 1.0f / (mx - mn);
    float4 ng;
    ng.x = (gv.x - mn) * inv; ng.y = (gv.y - mn) * inv;
    ng.z = (gv.z - mn) * inv; ng.w = (gv.w - mn) * inv;

    float sg = ng.x * ng.x + ng.y * ng.y + ng.z * ng.z + ng.w * ng.w;
    float sx = xv.x * xv.x + xv.y * xv.y + xv.z * xv.z + xv.w * xv.w;
#pragma unroll
    for (int o = 16; o > 0; o >>= 1) {
        sg += __shfl_xor_sync(0xffffffffu, sg, o);
        sx += __shfl_xor_sync(0xffffffffu, sx, o);
    }
    if (lane == 0) { ssg[w] = sg; ssx[w] = sx; }
    __syncthreads();
    sg = 0.f; sx = 0.f;
#pragma unroll
    for (int i = 0; i < 8; i++) { sg += ssg[i]; sx += ssx[i]; }

    const float rg = 1.0f / sqrtf(sg);
    const float rx = 1.0f / sqrtf(sx);

    // interleaved (g, x) pairs; each thread writes 32B contiguous
    float4 f0, f1;
    f0.x = ng.x * rg; f0.y = xv.x * rx; f0.z = ng.y * rg; f0.w = xv.y * rx;
    f1.x = ng.z * rg; f1.y = xv.z * rx; f1.z = ng.w * rg; f1.w = xv.w * rx;
    float4* pk = reinterpret_cast<float4*>(g_pk + (size_t)row * ND);
    pk[2 * tid + 0] = f0;
    pk[2 * tid + 1] = f1;

    if (tid == 0) {
        const float* o = outputs + row * NC;
        int best = 0; float bv = o[0];
#pragma unroll
        for (int c = 1; c < NC; c++) { float v = o[c]; if (v > bv) { bv = v; best = c; } }
        g_cls[row] = best;
        atomicAdd(&g_counts[best], 1);
    }
}

// ---------------- kernel 2: stable counting sort + tile queue ----------------
__global__ void __launch_bounds__(1024) k_scatter() {
    __shared__ int sbase[NC];
    __shared__ int wcnt[32][NC];
    __shared__ int woff[32][NC];
    __shared__ int tot[NC];
    const int t = threadIdx.x;
    const int lane = t & 31, w = t >> 5;

    if (t == 0) {
        int acc = 0;
        for (int c = 0; c < NC; c++) { g_offsets[c] = acc; sbase[c] = acc; acc += g_counts[c]; }
        // build the active-tile work queue (deterministic order)
        int nt = 0;
        for (int c = 0; c < NC; c++) {
            const int tl = (g_counts[c] + TILE - 1) / TILE;
            for (int ti = 0; ti < tl; ti++)
                for (int tj = ti; tj < tl; tj++)
                    g_tiles[nt++] = c | (ti << 4) | (tj << 10);
        }
        g_ntiles = nt;
    }
    __syncthreads();

    for (int chunk = 0; chunk < NB; chunk += 1024) {
        const int r = chunk + t;
        const int myc = g_cls[r];
        int rank = 0;
#pragma unroll
        for (int c = 0; c < NC; c++) {
            const unsigned m = __ballot_sync(0xffffffffu, myc == c);
            if (lane == 0) wcnt[w][c] = __popc(m);
            if (myc == c) rank = __popc(m & ((1u << lane) - 1u));
        }
        __syncthreads();
        if (w < NC) {   // warp w scans class w across the 32 warps
            const int v = wcnt[lane][w];
            int x = v;
#pragma unroll
            for (int o = 1; o < 32; o <<= 1) {
                const int y = __shfl_up_sync(0xffffffffu, x, o);
                if (lane >= o) x += y;
            }
            woff[lane][w] = x - v;
            if (lane == 31) tot[w] = x;
        }
        __syncthreads();
        g_order[sbase[myc] + woff[w][myc] + rank] = r;
        __syncthreads();
        if (w == 0 && lane < NC) sbase[lane] += tot[lane];
        __syncthreads();
    }
}

// ---------------- kernel 3: fused double-Gram + ratio sum ----------------
// Work-queue of active tiles. 256 threads = 16x16; each thread owns a 4x4
// micro-tile; both cosines advance together via packed f32x2 FMA.
// Double-buffered smem: one barrier per K-chunk; LDG prefetch + STS of chunk
// c+1 overlap compute of chunk c.
__global__ void __launch_bounds__(256, 2) k_gram() {
    __shared__ char As[2][TILE * 128];   // 64 rows x 8 float4 (g,x pairs), swizzled
    __shared__ char Bs[2][TILE * 128];
    __shared__ float red[256];

    const int t    = threadIdx.x;
    const int lrow = t >> 2;              // loader row 0..63
    const int lc   = (t & 3) * 2;         // loader float4 slot 0,2,4,6
    const int tx   = t & 15;
    const int ty   = t >> 4;

    const int ntiles = g_ntiles;
    const float4* gp = reinterpret_cast<const float4*>(g_pk);   // row stride 512 float4

    for (int idx = blockIdx.x; idx < ntiles; idx += gridDim.x) {
        const int desc = g_tiles[idx];
        const int c  = desc & 15;
        const int ti = (desc >> 4) & 63;
        const int tj = (desc >> 10) & 63;
        const int nc   = g_counts[c];
        const int base = g_offsets[c];

        const int aPos = ti * TILE + lrow;
        const int bPos = tj * TILE + lrow;
        const bool aV = aPos < nc;
        const bool bV = bPos < nc;
        const size_t aOff = aV ? (size_t)g_order[base + aPos] * 512 : 0;
        const size_t bOff = bV ? (size_t)g_order[base + bPos] * 512 : 0;
        const float4 z4 = make_float4(0.f, 0.f, 0.f, 0.f);

        unsigned long long acc[4][4];
#pragma unroll
        for (int i = 0; i < 4; i++)
#pragma unroll
            for (int j = 0; j < 4; j++) acc[i][j] = 0ull;

        // prologue: load + stage chunk 0 into buffer 0
        float4 pa0 = aV ? gp[aOff + lc]     : z4;
        float4 pa1 = aV ? gp[aOff + lc + 1] : z4;
        float4 pb0 = bV ? gp[bOff + lc]     : z4;
        float4 pb1 = bV ? gp[bOff + lc + 1] : z4;
        __syncthreads();                       // re-use safety across queue iterations
        *tile_ptr(As[0], lrow, lc)     = pa0;
        *tile_ptr(As[0], lrow, lc + 1) = pa1;
        *tile_ptr(Bs[0], lrow, lc)     = pb0;
        *tile_ptr(Bs[0], lrow, lc + 1) = pb1;
        __syncthreads();

        for (int ch = 0; ch < NCHUNK; ch++) {
            const int cur = ch & 1;
            const bool more = (ch + 1) < NCHUNK;

            if (more) {   // prefetch chunk ch+1 (overlaps compute below)
                const size_t nf = (size_t)(ch + 1) * (KC / 2);
                pa0 = aV ? gp[aOff + nf + lc]     : z4;
                pa1 = aV ? gp[aOff + nf + lc + 1] : z4;
                pb0 = bV ? gp[bOff + nf + lc]     : z4;
                pb1 = bV ? gp[bOff + nf + lc + 1] : z4;
            }

            char* Ab = As[cur];
            char* Bb = Bs[cur];
#pragma unroll
            for (int cc = 0; cc < 8; cc++) {        // 2 k per slot
                ulonglong2 a4[4], b4[4];
#pragma unroll
                for (int i = 0; i < 4; i++)
                    a4[i] = *reinterpret_cast<ulonglong2*>(tile_ptr(Ab, ty * 4 + i, cc));
#pragma unroll
                for (int j = 0; j < 4; j++)
                    b4[j] = *reinterpret_cast<ulonglong2*>(tile_ptr(Bb, tx + 16 * j, cc));
#pragma unroll
                for (int i = 0; i < 4; i++)
#pragma unroll
                    for (int j = 0; j < 4; j++) {
                        ffma2(acc[i][j], a4[i].x, b4[j].x);
                        ffma2(acc[i][j], a4[i].y, b4[j].y);
                    }
            }

            if (more) {   // stage chunk ch+1 into the other buffer
                char* An = As[cur ^ 1];
                char* Bn = Bs[cur ^ 1];
                *tile_ptr(An, lrow, lc)     = pa0;
                *tile_ptr(An, lrow, lc + 1) = pa1;
                *tile_ptr(Bn, lrow, lc)     = pb0;
                *tile_ptr(Bn, lrow, lc + 1) = pb1;
            }
            __syncthreads();
        }

        // masked ratio: pair valid iff both rows exist and rp < cp (strict upper)
        float sum = 0.f;
#pragma unroll
        for (int i = 0; i < 4; i++) {
            const int rp = ti * TILE + ty * 4 + i;
#pragma unroll
            for (int j = 0; j < 4; j++) {
                const int cp = tj * TILE + tx + 16 * j;
                if (rp < nc && cp < nc && rp < cp) {
                    const float cg = __uint_as_float((unsigned)(acc[i][j] & 0xffffffffu));
                    const float cx = __uint_as_float((unsigned)(acc[i][j] >> 32));
                    sum += (1.0f - cg) / (1.0f - cx);
                }
            }
        }

        red[t] = sum;
        __syncthreads();
#pragma unroll
        for (int s = 128; s > 0; s >>= 1) {
            if (t < s) red[t] += red[t + s];
            __syncthreads();
        }
        if (t == 0) g_partials[idx] = red[0];
    }
}

// ---------------- kernel 4: final deterministic reduction ----------------
__global__ void __launch_bounds__(256) k_final(float* __restrict__ out) {
    __shared__ float red[256];
    const int t = threadIdx.x;
    const int n = g_ntiles;
    float s = 0.f;
    for (int i = t; i < n; i += 256) s += g_partials[i];
    red[t] = s;
    __syncthreads();
#pragma unroll
    for (int st = 128; st > 0; st >>= 1) {
        if (t < st) red[t] += red[t + st];
        __syncthreads();
    }
    if (t == 0) out[0] = red[0] / (float)NB;
}

// ---------------- launch ----------------
extern "C" void kernel_launch(void* const* d_in, const int* in_sizes, int n_in,
                              void* d_out, int out_size) {
    (void)in_sizes; (void)n_in; (void)out_size;
    const float* outputs = (const float*)d_in[0];
    const float* grad    = (const float*)d_in[1];
    const float* xin     = (const float*)d_in[2];
    float* out = (float*)d_out;

    k_zero<<<1, 32>>>();
    k_prep<<<NB, 256>>>(outputs, grad, xin);
    k_scatter<<<1, 1024>>>();
    k_gram<<<GGRID, 256>>>();
    k_final<<<1, 256>>>(out);
}